// round 13
// baseline (speedup 1.0000x reference)
#include <cuda_runtime.h>
#include <cuda_fp16.h>
#include <cstdint>

#define HID  64
#define FEAT 9
#define TT   36
#define BLK  128
#define BPB  128

#define APITCH 64    // fp16 per A row (128 B)
#define BPITCH 64    // fp16 per B row (128 B)
#define DPITCH 36    // f32 per D row

// ---- smem byte layout ----
#define SM_A_HI 0
#define SM_A_LO 16384
#define SM_B_HI 32768
#define SM_B_LO 65536
#define SM_D    98304
#define SM_C    116736
#define SM_H    151552
#define SM_SCAL 186368
// scalar float offsets (relative to SM_SCAL)
#define FO_WGI   0      // [64][9 kp][4 gate][2 par] inp-part gate weights = 4608
#define FO_B2    4608   // [64][4] bias pairs (bias,0) = 512
#define FO_WGH   5120   // [64][9]
#define FO_BGH   5696
#define FO_WHIST 5760   // [9][64]
#define FO_BHIST 6336
#define FO_WGXD  6348
#define FO_BGX   6360
#define FO_WFEAT 6372
#define FO_BFEAT 6456
#define FO_WCOMB 6468
#define FO_BCOMB 6632
#define FO_INV   6644
#define SCAL_FLOATS 6680
#define SMEM_TOTAL (SM_SCAL + SCAL_FLOATS*4)   // 213088 B

__device__ float g_denom[TT];
__device__ float g_partials[1024];

typedef unsigned long long u64;

__device__ __forceinline__ void fma2(u64& acc, u64 a, u64 b) {
    asm("fma.rn.f32x2 %0, %1, %2, %0;" : "+l"(acc) : "l"(a), "l"(b));
}
__device__ __forceinline__ u64 pack2(float lo, float hi) {
    u64 r; asm("mov.b64 %0, {%1, %2};" : "=l"(r) : "f"(lo), "f"(hi)); return r;
}
__device__ __forceinline__ float2 unpack2(u64 v) {
    float2 r; asm("mov.b64 {%0, %1}, %2;" : "=f"(r.x), "=f"(r.y) : "l"(v)); return r;
}
__device__ __forceinline__ float fsigmoid(float x) {
    return __fdividef(1.0f, 1.0f + __expf(-x));
}
__device__ __forceinline__ float ftanhx(float x) {
    float e = __expf(2.0f * x);
    return 1.0f - __fdividef(2.0f, e + 1.0f);
}
__device__ __forceinline__ uint32_t smem_u32(const void* p) {
    uint32_t a;
    asm("{ .reg .u64 t; cvta.to.shared.u64 t, %1; cvt.u32.u64 %0, t; }" : "=r"(a) : "l"(p));
    return a;
}
__device__ __forceinline__ void ldsm_x4(uint32_t* r, uint32_t addr) {
    asm volatile("ldmatrix.sync.aligned.m8n8.x4.shared.b16 {%0,%1,%2,%3}, [%4];"
                 : "=r"(r[0]), "=r"(r[1]), "=r"(r[2]), "=r"(r[3]) : "r"(addr));
}
__device__ __forceinline__ void ldsm_x2(uint32_t* r, uint32_t addr) {
    asm volatile("ldmatrix.sync.aligned.m8n8.x2.shared.b16 {%0,%1}, [%2];"
                 : "=r"(r[0]), "=r"(r[1]) : "r"(addr));
}
__device__ __forceinline__ void mma16816(float* c, const uint32_t* a, const uint32_t* b) {
    asm volatile("mma.sync.aligned.m16n8k16.row.col.f32.f16.f16.f32 "
                 "{%0,%1,%2,%3}, {%4,%5,%6,%7}, {%8,%9}, {%0,%1,%2,%3};"
                 : "+f"(c[0]), "+f"(c[1]), "+f"(c[2]), "+f"(c[3])
                 : "r"(a[0]), "r"(a[1]), "r"(a[2]), "r"(a[3]), "r"(b[0]), "r"(b[1]));
}

// ---- denom kernels ----
__global__ void zero_denom_kernel() {
    if (threadIdx.x < TT) g_denom[threadIdx.x] = 0.0f;
}
__global__ void denom_kernel(const float* __restrict__ masks, int B) {
    __shared__ float bins[TT];
    if (threadIdx.x < TT) bins[threadIdx.x] = 0.0f;
    __syncthreads();
    int idx = blockIdx.x * blockDim.x + threadIdx.x;
    if (idx < B * TT) {
        int t = idx % TT;
        const float* p = masks + (size_t)idx * FEAT;
        float sv = 0.0f;
        #pragma unroll
        for (int f = 0; f < FEAT; f++) sv += p[f];
        atomicAdd(&bins[t], sv);
    }
    __syncthreads();
    if (threadIdx.x < TT) atomicAdd(&g_denom[threadIdx.x], bins[threadIdx.x]);
}

__global__ void __launch_bounds__(BLK, 1)
rits_main_kernel(const float* __restrict__ values,
                 const float* __restrict__ masks,
                 const float* __restrict__ deltas,
                 const float* __restrict__ Wgh, const float* __restrict__ bgh,
                 const float* __restrict__ Wgx, const float* __restrict__ bgx,
                 const float* __restrict__ Whist, const float* __restrict__ bhist,
                 const float* __restrict__ Wfeat, const float* __restrict__ bfeat,
                 const float* __restrict__ Wcomb, const float* __restrict__ bcomb,
                 const float* __restrict__ Wih, const float* __restrict__ Whh,
                 const float* __restrict__ bih, const float* __restrict__ bhh,
                 float* __restrict__ out, int B) {
    extern __shared__ char smem[];
    float* sfp = (float*)(smem + SM_SCAL);
    const int tid = threadIdx.x;
    const int w = tid >> 5;
    const int lane = tid & 31;
    const int b = blockIdx.x * BPB + tid;
    const uint32_t smb = smem_u32(smem);

    // ---- stage B (Whh only) hi/lo fp16: row n = 4j+g, k = 0..63 ----
    for (int idx = tid; idx < 256 * 64; idx += BLK) {
        int n = idx >> 6, k = idx & 63;
        int row = (n & 3) * HID + (n >> 2);
        float v = Whh[row * HID + k];
        __half h = __float2half(v);
        __half l = __float2half(v - __half2float(h));
        ((__half*)(smem + SM_B_HI))[n * BPITCH + k] = h;
        ((__half*)(smem + SM_B_LO))[n * BPITCH + k] = l;
    }
    // ---- stage inp-part gate weights [j][kp][g][p] (R7-proven layout) ----
    for (int idx = tid; idx < 64 * 72; idx += BLK) {
        int j = idx / 72, r = idx - j * 72;
        int kp = r >> 3, g = (r & 7) >> 1, p = r & 1;
        int k = 2 * kp + p;   // 0..17
        int row = g * HID + j;
        sfp[FO_WGI + idx] = Wih[row * 18 + k];
    }
    for (int idx = tid; idx < 256; idx += BLK) {
        int j = idx >> 2, g = idx & 3;
        sfp[FO_B2 + idx * 2]     = bih[g * HID + j] + bhh[g * HID + j];
        sfp[FO_B2 + idx * 2 + 1] = 0.0f;
    }
    for (int idx = tid; idx < 576; idx += BLK) {
        sfp[FO_WGH + idx] = Wgh[idx];
        sfp[FO_WHIST + idx] = Whist[idx];
    }
    for (int idx = tid; idx < 164; idx += BLK)
        sfp[FO_WCOMB + idx] = (idx < 162) ? Wcomb[idx] : 0.0f;
    if (tid < 64) sfp[FO_BGH + tid] = bgh[tid];
    if (tid < 12) {
        sfp[FO_BHIST + tid] = (tid < 9) ? bhist[tid] : 0.0f;
        sfp[FO_WGXD + tid]  = (tid < 9) ? Wgx[tid * FEAT + tid] : 0.0f;
        sfp[FO_BGX + tid]   = (tid < 9) ? bgx[tid] : 0.0f;
        sfp[FO_BFEAT + tid] = (tid < 9) ? bfeat[tid] : 0.0f;
        sfp[FO_BCOMB + tid] = (tid < 9) ? bcomb[tid] : 0.0f;
    }
    if (tid < 84) {
        int f = tid / 9, f2 = tid - f * 9;
        sfp[FO_WFEAT + tid] = (tid < 81 && f != f2) ? Wfeat[tid] : 0.0f;
    }
    if (tid < TT) sfp[FO_INV + tid] = 1.0f / (g_denom[tid] + 1e-5f);

    float* myc = (float*)(smem + SM_C) + tid * 68;
    float* myh = (float*)(smem + SM_H) + tid * 68;
    #pragma unroll
    for (int k = 0; k < 64; k++) { myc[k] = 0.0f; myh[k] = 0.0f; }
    __syncthreads();

    const int bb = (b < B) ? b : (B - 1);
    const bool active = (b < B);
    const float* xb = values + (size_t)bb * (TT * FEAT);
    const float* mb = masks + (size_t)bb * (TT * FEAT);
    const float* db = deltas + (size_t)bb * (TT * FEAT);
    float* ob = out + 1 + (size_t)bb * (TT * FEAT);

    char* aHiRow = (char*)smem + SM_A_HI + (size_t)tid * 128;
    char* aLoRow = (char*)smem + SM_A_LO + (size_t)tid * 128;
    const uint32_t aFragOff = (uint32_t)(w * 32 + (lane & 15)) * 128 + (lane & 16);
    const uint32_t bFragOff = (uint32_t)(lane & 7) * 128 + ((lane & 8) << 1);
    const uint32_t aHiBase = smb + SM_A_HI + aFragOff;
    const uint32_t aLoBase = smb + SM_A_LO + aFragOff;
    const uint32_t bHiBase = smb + SM_B_HI + bFragOff;
    const uint32_t bLoBase = smb + SM_B_LO + bFragOff;
    float* dRow = (float*)(smem + SM_D) + tid * DPITCH;
    float* dWr0 = (float*)(smem + SM_D) + (w * 32 + (lane >> 2)) * DPITCH + 2 * (lane & 3);
    float* dWr1 = dWr0 + 8 * DPITCH;

    float loss = 0.0f;
    #pragma unroll 1
    for (int t = 0; t < TT; t++) {
        float x[9], m[9], d[9];
        #pragma unroll
        for (int f = 0; f < 9; f++) {
            x[f] = xb[t * 9 + f];
            m[f] = mb[t * 9 + f];
            d[f] = db[t * 9 + f];
        }

        // ---- decay: hreg = myh * exp(-relu(d @ Wgh^T + bgh)) ----
        float hreg[64];
        #pragma unroll
        for (int q = 0; q < 16; q++) {
            const float* w0 = sfp + FO_WGH + (4 * q) * 9;
            float a0 = sfp[FO_BGH + 4 * q];
            float a1 = sfp[FO_BGH + 4 * q + 1];
            float a2 = sfp[FO_BGH + 4 * q + 2];
            float a3 = sfp[FO_BGH + 4 * q + 3];
            #pragma unroll
            for (int f = 0; f < 9; f++) {
                float dv = d[f];
                a0 = fmaf(dv, w0[f], a0);
                a1 = fmaf(dv, w0[9 + f], a1);
                a2 = fmaf(dv, w0[18 + f], a2);
                a3 = fmaf(dv, w0[27 + f], a3);
            }
            float4 hv = *(const float4*)(myh + 4 * q);
            hreg[4 * q]     = hv.x * __expf(-fmaxf(a0, 0.0f));
            hreg[4 * q + 1] = hv.y * __expf(-fmaxf(a1, 0.0f));
            hreg[4 * q + 2] = hv.z * __expf(-fmaxf(a2, 0.0f));
            hreg[4 * q + 3] = hv.w * __expf(-fmaxf(a3, 0.0f));
        }

        // ---- history regression x_h ----
        float xh[9];
        #pragma unroll
        for (int f = 0; f < 9; f++) {
            const float* wv = sfp + FO_WHIST + f * 64;
            float a0 = sfp[FO_BHIST + f], a1 = 0.0f, a2 = 0.0f, a3 = 0.0f;
            #pragma unroll
            for (int q = 0; q < 16; q++) {
                a0 = fmaf(hreg[4 * q],     wv[4 * q],     a0);
                a1 = fmaf(hreg[4 * q + 1], wv[4 * q + 1], a1);
                a2 = fmaf(hreg[4 * q + 2], wv[4 * q + 2], a2);
                a3 = fmaf(hreg[4 * q + 3], wv[4 * q + 3], a3);
            }
            xh[f] = (a0 + a1) + (a2 + a3);
        }

        float xc[9], gx[9];
        #pragma unroll
        for (int f = 0; f < 9; f++) {
            xc[f] = m[f] * x[f] + (1.0f - m[f]) * xh[f];
            gx[f] = __expf(-fmaxf(fmaf(d[f], sfp[FO_WGXD + f], sfp[FO_BGX + f]), 0.0f));
        }

        float inp[18];
        float lsum = 0.0f;
        #pragma unroll
        for (int f = 0; f < 9; f++) {
            const float* wf = sfp + FO_WFEAT + f * 9;
            float zh = sfp[FO_BFEAT + f];
            #pragma unroll
            for (int k = 0; k < 9; k++) zh = fmaf(xc[k], wf[k], zh);
            const float* wc = sfp + FO_WCOMB + f * 18;
            float al = sfp[FO_BCOMB + f];
            #pragma unroll
            for (int k = 0; k < 9; k++) al = fmaf(gx[k], wc[k], al);
            #pragma unroll
            for (int k = 0; k < 9; k++) al = fmaf(m[k], wc[9 + k], al);
            float ch = al * zh + (1.0f - al) * xh[f];
            lsum += m[f] * (fabsf(x[f] - xh[f]) + fabsf(x[f] - zh) + fabsf(x[f] - ch));
            float c_c = m[f] * x[f] + (1.0f - m[f]) * ch;
            if (active) ob[t * 9 + f] = c_c;
            inp[f] = c_c;
            inp[9 + f] = m[f];
        }
        if (active) loss = fmaf(lsum, sfp[FO_INV + t], loss);

        u64 inpp[9];
        #pragma unroll
        for (int kp = 0; kp < 9; kp++) inpp[kp] = pack2(inp[2 * kp], inp[2 * kp + 1]);

        // ---- pack A row = decayed h only (64 fp16, hi/lo) ----
        #pragma unroll
        for (int i = 0; i < 8; i++) {
            uint32_t hi4[4], lo4[4];
            #pragma unroll
            for (int p = 0; p < 4; p++) {
                const int c0 = 8 * i + 2 * p;
                float v0 = hreg[c0], v1 = hreg[c0 + 1];
                __half h0 = __float2half(v0);
                __half h1 = __float2half(v1);
                __half l0 = __float2half(v0 - __half2float(h0));
                __half l1 = __float2half(v1 - __half2float(h1));
                hi4[p] = ((uint32_t)__half_as_ushort(h1) << 16) | __half_as_ushort(h0);
                lo4[p] = ((uint32_t)__half_as_ushort(l1) << 16) | __half_as_ushort(l0);
            }
            *(uint4*)(aHiRow + 16 * i) = make_uint4(hi4[0], hi4[1], hi4[2], hi4[3]);
            *(uint4*)(aLoRow + 16 * i) = make_uint4(lo4[0], lo4[1], lo4[2], lo4[3]);
        }
        __syncthreads();

        // ---- h @ Whh^T via MMA, 8 chunks of 4 N-tiles ----
        #pragma unroll 1
        for (int chunk = 0; chunk < 8; chunk++) {
            float acc[2][4][4];
            #pragma unroll
            for (int mt = 0; mt < 2; mt++)
                #pragma unroll
                for (int nt = 0; nt < 4; nt++)
                    #pragma unroll
                    for (int e = 0; e < 4; e++) acc[mt][nt][e] = 0.0f;

            #pragma unroll
            for (int kt = 0; kt < 4; kt++) {
                uint32_t ah0[4], ah1[4], al0[4], al1[4];
                ldsm_x4(ah0, aHiBase + kt * 32);
                ldsm_x4(ah1, aHiBase + 16 * 128 + kt * 32);
                ldsm_x4(al0, aLoBase + kt * 32);
                ldsm_x4(al1, aLoBase + 16 * 128 + kt * 32);
                #pragma unroll
                for (int ntl = 0; ntl < 4; ntl++) {
                    const uint32_t nOff = (uint32_t)(chunk * 4 + ntl) * 8 * 128 + kt * 32;
                    uint32_t bh[2], bl[2];
                    ldsm_x2(bh, bHiBase + nOff);
                    ldsm_x2(bl, bLoBase + nOff);
                    mma16816(acc[0][ntl], ah0, bh);
                    mma16816(acc[0][ntl], ah0, bl);
                    mma16816(acc[0][ntl], al0, bh);
                    mma16816(acc[0][ntl], al0, bl);
                    mma16816(acc[1][ntl], ah1, bh);
                    mma16816(acc[1][ntl], ah1, bl);
                    mma16816(acc[1][ntl], al1, bh);
                    mma16816(acc[1][ntl], al1, bl);
                }
            }
            #pragma unroll
            for (int mt = 0; mt < 2; mt++) {
                #pragma unroll
                for (int ntl = 0; ntl < 4; ntl++) {
                    float* p0 = dWr0 + mt * 16 * DPITCH + ntl * 8;
                    float* p1 = dWr1 + mt * 16 * DPITCH + ntl * 8;
                    *(float2*)p0 = make_float2(acc[mt][ntl][0], acc[mt][ntl][1]);
                    *(float2*)p1 = make_float2(acc[mt][ntl][2], acc[mt][ntl][3]);
                }
            }
            __syncthreads();

            // ---- epilogue: scalar inp+bias part (R7 path) + MMA h-part ----
            #pragma unroll
            for (int u = 0; u < 8; u++) {
                const int j = chunk * 8 + u;
                const ulonglong2* wj = (const ulonglong2*)(sfp + FO_WGI + j * 72);
                const ulonglong2* bj = (const ulonglong2*)(sfp + FO_B2 + j * 8);
                ulonglong2 b0 = bj[0], b1 = bj[1];
                u64 aI = b0.x, aF = b0.y, aG = b1.x, aO = b1.y;
                #pragma unroll
                for (int kp = 0; kp < 9; kp++) {
                    ulonglong2 w0 = wj[2 * kp];
                    ulonglong2 w1 = wj[2 * kp + 1];
                    u64 xv = inpp[kp];
                    fma2(aI, xv, w0.x);
                    fma2(aF, xv, w0.y);
                    fma2(aG, xv, w1.x);
                    fma2(aO, xv, w1.y);
                }
                float2 vi = unpack2(aI), vf = unpack2(aF);
                float2 vg = unpack2(aG), vo = unpack2(aO);
                float gi = vi.x + vi.y + dRow[4 * u + 0];
                float gf = vf.x + vf.y + dRow[4 * u + 1];
                float gg = vg.x + vg.y + dRow[4 * u + 2];
                float go = vo.x + vo.y + dRow[4 * u + 3];
                float cn = fsigmoid(gf) * myc[j] + fsigmoid(gi) * ftanhx(gg);
                myc[j] = cn;
                myh[j] = fsigmoid(go) * ftanhx(cn);
            }
            __syncthreads();
        }
    }

    // deterministic block reduction of loss
    #pragma unroll
    for (int o = 16; o; o >>= 1) loss += __shfl_down_sync(~0u, loss, o);
    __shared__ float red[4];
    if ((tid & 31) == 0) red[tid >> 5] = loss;
    __syncthreads();
    if (tid == 0) g_partials[blockIdx.x] = (red[0] + red[1]) + (red[2] + red[3]);
}

__global__ void finalize_kernel(float* __restrict__ out, int nblocks) {
    float sv = 0.0f;
    for (int i = threadIdx.x; i < nblocks; i += 256) sv += g_partials[i];
    __shared__ float red[8];
    #pragma unroll
    for (int o = 16; o; o >>= 1) sv += __shfl_down_sync(~0u, sv, o);
    if ((threadIdx.x & 31) == 0) red[threadIdx.x >> 5] = sv;
    __syncthreads();
    if (threadIdx.x < 8) {
        sv = red[threadIdx.x];
        #pragma unroll
        for (int o = 4; o; o >>= 1) sv += __shfl_down_sync(0xff, sv, o);
        if (threadIdx.x == 0) out[0] = sv * (1.0f / (float)TT);
    }
}

extern "C" void kernel_launch(void* const* d_in, const int* in_sizes, int n_in,
                              void* d_out, int out_size) {
    const float* values = (const float*)d_in[0];
    const float* masks  = (const float*)d_in[1];
    const float* deltas = (const float*)d_in[2];
    const float* Wgh   = (const float*)d_in[3];
    const float* bgh   = (const float*)d_in[4];
    const float* Wgx   = (const float*)d_in[5];
    const float* bgx   = (const float*)d_in[6];
    const float* Whist = (const float*)d_in[7];
    const float* bhist = (const float*)d_in[8];
    const float* Wfeat = (const float*)d_in[9];
    const float* bfeat = (const float*)d_in[10];
    const float* Wcomb = (const float*)d_in[11];
    const float* bcomb = (const float*)d_in[12];
    const float* Wih   = (const float*)d_in[13];
    const float* Whh   = (const float*)d_in[14];
    const float* bih   = (const float*)d_in[15];
    const float* bhh   = (const float*)d_in[16];
    float* out = (float*)d_out;

    int B = in_sizes[0] / (TT * FEAT);
    int nb = (B + BPB - 1) / BPB;

    cudaFuncSetAttribute(rits_main_kernel,
                         cudaFuncAttributeMaxDynamicSharedMemorySize, SMEM_TOTAL);

    zero_denom_kernel<<<1, 64>>>();
    denom_kernel<<<(B * TT + 255) / 256, 256>>>(masks, B);
    rits_main_kernel<<<nb, BLK, SMEM_TOTAL>>>(
        values, masks, deltas, Wgh, bgh, Wgx, bgx, Whist, bhist,
        Wfeat, bfeat, Wcomb, bcomb, Wih, Whh, bih, bhh, out, B);
    finalize_kernel<<<1, 256>>>(out, nb);
}

// round 14
// speedup vs baseline: 1.3414x; 1.3414x over previous
#include <cuda_runtime.h>
#include <cuda_fp16.h>
#include <cstdint>

#define HID  64
#define FEAT 9
#define TT   36
#define BLK  128
#define BPB  128

#define DPITCH 68    // f32 per D row (64 cols + pad, 16B aligned)

// ---- smem byte layout ----
#define SM_A_HI 0
#define SM_A_LO 16384
#define SM_B_HI 32768
#define SM_B_LO 65536
#define SM_D    98304
#define SM_C    133120
#define SM_H    167936
#define SM_SCAL 202752
// scalar float offsets (relative to SM_SCAL)
#define FO_WGI   0      // [64][9 kp][4 gate][2 par] inp-part gate weights = 4608
#define FO_B2    4608   // [64][4] bias pairs (bias,0) = 512
#define FO_WGH   5120   // [64][9]
#define FO_BGH   5696
#define FO_WHIST 5760   // [9][64]
#define FO_BHIST 6336
#define FO_WGXD  6348
#define FO_BGX   6360
#define FO_WFEAT 6372
#define FO_BFEAT 6456
#define FO_WCOMB 6468
#define FO_BCOMB 6632
#define FO_INV   6644
#define SCAL_FLOATS 6680
#define SMEM_TOTAL (SM_SCAL + SCAL_FLOATS*4)   // 229472 B

__device__ float g_denom[TT];
__device__ float g_partials[1024];

typedef unsigned long long u64;

__device__ __forceinline__ void fma2(u64& acc, u64 a, u64 b) {
    asm("fma.rn.f32x2 %0, %1, %2, %0;" : "+l"(acc) : "l"(a), "l"(b));
}
__device__ __forceinline__ u64 pack2(float lo, float hi) {
    u64 r; asm("mov.b64 %0, {%1, %2};" : "=l"(r) : "f"(lo), "f"(hi)); return r;
}
__device__ __forceinline__ float2 unpack2(u64 v) {
    float2 r; asm("mov.b64 {%0, %1}, %2;" : "=f"(r.x), "=f"(r.y) : "l"(v)); return r;
}
__device__ __forceinline__ float fsigmoid(float x) {
    return __fdividef(1.0f, 1.0f + __expf(-x));
}
__device__ __forceinline__ float ftanhx(float x) {
    float e = __expf(2.0f * x);
    return 1.0f - __fdividef(2.0f, e + 1.0f);
}
__device__ __forceinline__ uint32_t smem_u32(const void* p) {
    uint32_t a;
    asm("{ .reg .u64 t; cvta.to.shared.u64 t, %1; cvt.u32.u64 %0, t; }" : "=r"(a) : "l"(p));
    return a;
}
__device__ __forceinline__ void ldsm_x4(uint32_t* r, uint32_t addr) {
    asm volatile("ldmatrix.sync.aligned.m8n8.x4.shared.b16 {%0,%1,%2,%3}, [%4];"
                 : "=r"(r[0]), "=r"(r[1]), "=r"(r[2]), "=r"(r[3]) : "r"(addr));
}
__device__ __forceinline__ void ldsm_x2(uint32_t* r, uint32_t addr) {
    asm volatile("ldmatrix.sync.aligned.m8n8.x2.shared.b16 {%0,%1}, [%2];"
                 : "=r"(r[0]), "=r"(r[1]) : "r"(addr));
}
__device__ __forceinline__ void mma16816(float* c, const uint32_t* a, const uint32_t* b) {
    asm volatile("mma.sync.aligned.m16n8k16.row.col.f32.f16.f16.f32 "
                 "{%0,%1,%2,%3}, {%4,%5,%6,%7}, {%8,%9}, {%0,%1,%2,%3};"
                 : "+f"(c[0]), "+f"(c[1]), "+f"(c[2]), "+f"(c[3])
                 : "r"(a[0]), "r"(a[1]), "r"(a[2]), "r"(a[3]), "r"(b[0]), "r"(b[1]));
}

// ---- denom kernels ----
__global__ void zero_denom_kernel() {
    if (threadIdx.x < TT) g_denom[threadIdx.x] = 0.0f;
}
__global__ void denom_kernel(const float* __restrict__ masks, int B) {
    __shared__ float bins[TT];
    if (threadIdx.x < TT) bins[threadIdx.x] = 0.0f;
    __syncthreads();
    int idx = blockIdx.x * blockDim.x + threadIdx.x;
    if (idx < B * TT) {
        int t = idx % TT;
        const float* p = masks + (size_t)idx * FEAT;
        float sv = 0.0f;
        #pragma unroll
        for (int f = 0; f < FEAT; f++) sv += p[f];
        atomicAdd(&bins[t], sv);
    }
    __syncthreads();
    if (threadIdx.x < TT) atomicAdd(&g_denom[threadIdx.x], bins[threadIdx.x]);
}

__global__ void __launch_bounds__(BLK, 1)
rits_main_kernel(const float* __restrict__ values,
                 const float* __restrict__ masks,
                 const float* __restrict__ deltas,
                 const float* __restrict__ Wgh, const float* __restrict__ bgh,
                 const float* __restrict__ Wgx, const float* __restrict__ bgx,
                 const float* __restrict__ Whist, const float* __restrict__ bhist,
                 const float* __restrict__ Wfeat, const float* __restrict__ bfeat,
                 const float* __restrict__ Wcomb, const float* __restrict__ bcomb,
                 const float* __restrict__ Wih, const float* __restrict__ Whh,
                 const float* __restrict__ bih, const float* __restrict__ bhh,
                 float* __restrict__ out, int B) {
    extern __shared__ char smem[];
    float* sfp = (float*)(smem + SM_SCAL);
    const int tid = threadIdx.x;
    const int w = tid >> 5;
    const int lane = tid & 31;
    const int b = blockIdx.x * BPB + tid;
    const uint32_t smb = smem_u32(smem);

    // ---- stage B (Whh only) hi/lo fp16: row n = 4j+g, k = 0..63 ----
    for (int idx = tid; idx < 256 * 64; idx += BLK) {
        int n = idx >> 6, k = idx & 63;
        int row = (n & 3) * HID + (n >> 2);
        float v = Whh[row * HID + k];
        __half h = __float2half(v);
        __half l = __float2half(v - __half2float(h));
        ((__half*)(smem + SM_B_HI))[n * 64 + k] = h;
        ((__half*)(smem + SM_B_LO))[n * 64 + k] = l;
    }
    // ---- stage inp-part gate weights [j][kp][g][p] (R7-proven layout) ----
    for (int idx = tid; idx < 64 * 72; idx += BLK) {
        int j = idx / 72, r = idx - j * 72;
        int kp = r >> 3, g = (r & 7) >> 1, p = r & 1;
        int k = 2 * kp + p;   // 0..17
        int row = g * HID + j;
        sfp[FO_WGI + idx] = Wih[row * 18 + k];
    }
    for (int idx = tid; idx < 256; idx += BLK) {
        int j = idx >> 2, g = idx & 3;
        sfp[FO_B2 + idx * 2]     = bih[g * HID + j] + bhh[g * HID + j];
        sfp[FO_B2 + idx * 2 + 1] = 0.0f;
    }
    for (int idx = tid; idx < 576; idx += BLK) {
        sfp[FO_WGH + idx] = Wgh[idx];
        sfp[FO_WHIST + idx] = Whist[idx];
    }
    for (int idx = tid; idx < 164; idx += BLK)
        sfp[FO_WCOMB + idx] = (idx < 162) ? Wcomb[idx] : 0.0f;
    if (tid < 64) sfp[FO_BGH + tid] = bgh[tid];
    if (tid < 12) {
        sfp[FO_BHIST + tid] = (tid < 9) ? bhist[tid] : 0.0f;
        sfp[FO_WGXD + tid]  = (tid < 9) ? Wgx[tid * FEAT + tid] : 0.0f;
        sfp[FO_BGX + tid]   = (tid < 9) ? bgx[tid] : 0.0f;
        sfp[FO_BFEAT + tid] = (tid < 9) ? bfeat[tid] : 0.0f;
        sfp[FO_BCOMB + tid] = (tid < 9) ? bcomb[tid] : 0.0f;
    }
    if (tid < 84) {
        int f = tid / 9, f2 = tid - f * 9;
        sfp[FO_WFEAT + tid] = (tid < 81 && f != f2) ? Wfeat[tid] : 0.0f;
    }
    if (tid < TT) sfp[FO_INV + tid] = 1.0f / (g_denom[tid] + 1e-5f);

    float* myc = (float*)(smem + SM_C) + tid * 68;
    float* myh = (float*)(smem + SM_H) + tid * 68;
    #pragma unroll
    for (int k = 0; k < 64; k++) { myc[k] = 0.0f; myh[k] = 0.0f; }
    __syncthreads();

    const int bb = (b < B) ? b : (B - 1);
    const bool active = (b < B);
    const float* xb = values + (size_t)bb * (TT * FEAT);
    const float* mb = masks + (size_t)bb * (TT * FEAT);
    const float* db = deltas + (size_t)bb * (TT * FEAT);
    float* ob = out + 1 + (size_t)bb * (TT * FEAT);

    char* aHiRow = (char*)smem + SM_A_HI + (size_t)tid * 128;
    char* aLoRow = (char*)smem + SM_A_LO + (size_t)tid * 128;
    const uint32_t aFragOff = (uint32_t)(w * 32 + (lane & 15)) * 128 + (lane & 16);
    const uint32_t bFragOff = (uint32_t)(lane & 7) * 128 + ((lane & 8) << 1);
    const uint32_t aHiBase = smb + SM_A_HI + aFragOff;
    const uint32_t aLoBase = smb + SM_A_LO + aFragOff;
    const uint32_t bHiBase = smb + SM_B_HI + bFragOff;
    const uint32_t bLoBase = smb + SM_B_LO + bFragOff;
    float* dRow = (float*)(smem + SM_D) + tid * DPITCH;
    float* dWr0 = (float*)(smem + SM_D) + (w * 32 + (lane >> 2)) * DPITCH + 2 * (lane & 3);
    float* dWr1 = dWr0 + 8 * DPITCH;

    float loss = 0.0f;
    #pragma unroll 1
    for (int t = 0; t < TT; t++) {
        float x[9], m[9], d[9];
        #pragma unroll
        for (int f = 0; f < 9; f++) {
            x[f] = xb[t * 9 + f];
            m[f] = mb[t * 9 + f];
            d[f] = db[t * 9 + f];
        }

        // ---- decay: hreg = myh * exp(-relu(d @ Wgh^T + bgh)) ----
        float hreg[64];
        #pragma unroll
        for (int q = 0; q < 16; q++) {
            const float* w0 = sfp + FO_WGH + (4 * q) * 9;
            float a0 = sfp[FO_BGH + 4 * q];
            float a1 = sfp[FO_BGH + 4 * q + 1];
            float a2 = sfp[FO_BGH + 4 * q + 2];
            float a3 = sfp[FO_BGH + 4 * q + 3];
            #pragma unroll
            for (int f = 0; f < 9; f++) {
                float dv = d[f];
                a0 = fmaf(dv, w0[f], a0);
                a1 = fmaf(dv, w0[9 + f], a1);
                a2 = fmaf(dv, w0[18 + f], a2);
                a3 = fmaf(dv, w0[27 + f], a3);
            }
            float4 hv = *(const float4*)(myh + 4 * q);
            hreg[4 * q]     = hv.x * __expf(-fmaxf(a0, 0.0f));
            hreg[4 * q + 1] = hv.y * __expf(-fmaxf(a1, 0.0f));
            hreg[4 * q + 2] = hv.z * __expf(-fmaxf(a2, 0.0f));
            hreg[4 * q + 3] = hv.w * __expf(-fmaxf(a3, 0.0f));
        }

        // ---- history regression x_h ----
        float xh[9];
        #pragma unroll
        for (int f = 0; f < 9; f++) {
            const float* wv = sfp + FO_WHIST + f * 64;
            float a0 = sfp[FO_BHIST + f], a1 = 0.0f, a2 = 0.0f, a3 = 0.0f;
            #pragma unroll
            for (int q = 0; q < 16; q++) {
                a0 = fmaf(hreg[4 * q],     wv[4 * q],     a0);
                a1 = fmaf(hreg[4 * q + 1], wv[4 * q + 1], a1);
                a2 = fmaf(hreg[4 * q + 2], wv[4 * q + 2], a2);
                a3 = fmaf(hreg[4 * q + 3], wv[4 * q + 3], a3);
            }
            xh[f] = (a0 + a1) + (a2 + a3);
        }

        float xc[9], gx[9];
        #pragma unroll
        for (int f = 0; f < 9; f++) {
            xc[f] = m[f] * x[f] + (1.0f - m[f]) * xh[f];
            gx[f] = __expf(-fmaxf(fmaf(d[f], sfp[FO_WGXD + f], sfp[FO_BGX + f]), 0.0f));
        }

        float inp[18];
        float lsum = 0.0f;
        #pragma unroll
        for (int f = 0; f < 9; f++) {
            const float* wf = sfp + FO_WFEAT + f * 9;
            float zh = sfp[FO_BFEAT + f];
            #pragma unroll
            for (int k = 0; k < 9; k++) zh = fmaf(xc[k], wf[k], zh);
            const float* wc = sfp + FO_WCOMB + f * 18;
            float al = sfp[FO_BCOMB + f];
            #pragma unroll
            for (int k = 0; k < 9; k++) al = fmaf(gx[k], wc[k], al);
            #pragma unroll
            for (int k = 0; k < 9; k++) al = fmaf(m[k], wc[9 + k], al);
            float ch = al * zh + (1.0f - al) * xh[f];
            lsum += m[f] * (fabsf(x[f] - xh[f]) + fabsf(x[f] - zh) + fabsf(x[f] - ch));
            float c_c = m[f] * x[f] + (1.0f - m[f]) * ch;
            if (active) ob[t * 9 + f] = c_c;
            inp[f] = c_c;
            inp[9 + f] = m[f];
        }
        if (active) loss = fmaf(lsum, sfp[FO_INV + t], loss);

        u64 inpp[9];
        #pragma unroll
        for (int kp = 0; kp < 9; kp++) inpp[kp] = pack2(inp[2 * kp], inp[2 * kp + 1]);

        // ---- pack A row = decayed h only (64 fp16, hi/lo) ----
        #pragma unroll
        for (int i = 0; i < 8; i++) {
            uint32_t hi4[4], lo4[4];
            #pragma unroll
            for (int p = 0; p < 4; p++) {
                const int c0 = 8 * i + 2 * p;
                float v0 = hreg[c0], v1 = hreg[c0 + 1];
                __half h0 = __float2half(v0);
                __half h1 = __float2half(v1);
                __half l0 = __float2half(v0 - __half2float(h0));
                __half l1 = __float2half(v1 - __half2float(h1));
                hi4[p] = ((uint32_t)__half_as_ushort(h1) << 16) | __half_as_ushort(h0);
                lo4[p] = ((uint32_t)__half_as_ushort(l1) << 16) | __half_as_ushort(l0);
            }
            *(uint4*)(aHiRow + 16 * i) = make_uint4(hi4[0], hi4[1], hi4[2], hi4[3]);
            *(uint4*)(aLoRow + 16 * i) = make_uint4(lo4[0], lo4[1], lo4[2], lo4[3]);
        }
        __syncthreads();   // insurance barrier (A-pack -> ldsm is within-warp)

        // ---- A fragments loaded ONCE per step ----
        uint32_t ah0[4][4], ah1[4][4], al0[4][4], al1[4][4];
        #pragma unroll
        for (int kt = 0; kt < 4; kt++) {
            ldsm_x4(ah0[kt], aHiBase + kt * 32);
            ldsm_x4(ah1[kt], aHiBase + 16 * 128 + kt * 32);
            ldsm_x4(al0[kt], aLoBase + kt * 32);
            ldsm_x4(al1[kt], aLoBase + 16 * 128 + kt * 32);
        }

        // ---- 4 chunks of 16 units (64 N cols each), 3 products ----
        #pragma unroll 1
        for (int c = 0; c < 4; c++) {
            float acc[2][8][4];
            #pragma unroll
            for (int mt = 0; mt < 2; mt++)
                #pragma unroll
                for (int nt = 0; nt < 8; nt++)
                    #pragma unroll
                    for (int e = 0; e < 4; e++) acc[mt][nt][e] = 0.0f;

            #pragma unroll
            for (int kt = 0; kt < 4; kt++) {
                #pragma unroll
                for (int ntl = 0; ntl < 8; ntl++) {
                    const uint32_t nOff = (uint32_t)(c * 8 + ntl) * 8 * 128 + kt * 32;
                    uint32_t bh[2], bl[2];
                    ldsm_x2(bh, bHiBase + nOff);
                    ldsm_x2(bl, bLoBase + nOff);
                    mma16816(acc[0][ntl], ah0[kt], bh);
                    mma16816(acc[0][ntl], ah0[kt], bl);
                    mma16816(acc[0][ntl], al0[kt], bh);
                    mma16816(acc[1][ntl], ah1[kt], bh);
                    mma16816(acc[1][ntl], ah1[kt], bl);
                    mma16816(acc[1][ntl], al1[kt], bh);
                }
            }
            #pragma unroll
            for (int mt = 0; mt < 2; mt++) {
                #pragma unroll
                for (int ntl = 0; ntl < 8; ntl++) {
                    float* p0 = dWr0 + mt * 16 * DPITCH + ntl * 8;
                    float* p1 = dWr1 + mt * 16 * DPITCH + ntl * 8;
                    *(float2*)p0 = make_float2(acc[mt][ntl][0], acc[mt][ntl][1]);
                    *(float2*)p1 = make_float2(acc[mt][ntl][2], acc[mt][ntl][3]);
                }
            }
            __syncwarp();   // D write->read: same warp's row block

            // ---- epilogue: 16 units; scalar inp+bias (R7 path) + MMA h-part ----
            #pragma unroll
            for (int u = 0; u < 16; u++) {
                const int j = c * 16 + u;
                const ulonglong2* wj = (const ulonglong2*)(sfp + FO_WGI + j * 72);
                const ulonglong2* bj = (const ulonglong2*)(sfp + FO_B2 + j * 8);
                ulonglong2 b0 = bj[0], b1 = bj[1];
                u64 aI = b0.x, aF = b0.y, aG = b1.x, aO = b1.y;
                #pragma unroll
                for (int kp = 0; kp < 9; kp++) {
                    ulonglong2 w0 = wj[2 * kp];
                    ulonglong2 w1 = wj[2 * kp + 1];
                    u64 xv = inpp[kp];
                    fma2(aI, xv, w0.x);
                    fma2(aF, xv, w0.y);
                    fma2(aG, xv, w1.x);
                    fma2(aO, xv, w1.y);
                }
                float4 dv = *(const float4*)(dRow + 4 * u);
                float2 vi = unpack2(aI), vf = unpack2(aF);
                float2 vg = unpack2(aG), vo = unpack2(aO);
                float gi = vi.x + vi.y + dv.x;
                float gf = vf.x + vf.y + dv.y;
                float gg = vg.x + vg.y + dv.z;
                float go = vo.x + vo.y + dv.w;
                float cn = fsigmoid(gf) * myc[j] + fsigmoid(gi) * ftanhx(gg);
                myc[j] = cn;
                myh[j] = fsigmoid(go) * ftanhx(cn);
            }
            __syncwarp();   // protect D before next chunk overwrites
        }
    }

    // deterministic block reduction of loss
    #pragma unroll
    for (int o = 16; o; o >>= 1) loss += __shfl_down_sync(~0u, loss, o);
    __shared__ float red[4];
    if ((tid & 31) == 0) red[tid >> 5] = loss;
    __syncthreads();
    if (tid == 0) g_partials[blockIdx.x] = (red[0] + red[1]) + (red[2] + red[3]);
}

__global__ void finalize_kernel(float* __restrict__ out, int nblocks) {
    float sv = 0.0f;
    for (int i = threadIdx.x; i < nblocks; i += 256) sv += g_partials[i];
    __shared__ float red[8];
    #pragma unroll
    for (int o = 16; o; o >>= 1) sv += __shfl_down_sync(~0u, sv, o);
    if ((threadIdx.x & 31) == 0) red[threadIdx.x >> 5] = sv;
    __syncthreads();
    if (threadIdx.x < 8) {
        sv = red[threadIdx.x];
        #pragma unroll
        for (int o = 4; o; o >>= 1) sv += __shfl_down_sync(0xff, sv, o);
        if (threadIdx.x == 0) out[0] = sv * (1.0f / (float)TT);
    }
}

extern "C" void kernel_launch(void* const* d_in, const int* in_sizes, int n_in,
                              void* d_out, int out_size) {
    const float* values = (const float*)d_in[0];
    const float* masks  = (const float*)d_in[1];
    const float* deltas = (const float*)d_in[2];
    const float* Wgh   = (const float*)d_in[3];
    const float* bgh   = (const float*)d_in[4];
    const float* Wgx   = (const float*)d_in[5];
    const float* bgx   = (const float*)d_in[6];
    const float* Whist = (const float*)d_in[7];
    const float* bhist = (const float*)d_in[8];
    const float* Wfeat = (const float*)d_in[9];
    const float* bfeat = (const float*)d_in[10];
    const float* Wcomb = (const float*)d_in[11];
    const float* bcomb = (const float*)d_in[12];
    const float* Wih   = (const float*)d_in[13];
    const float* Whh   = (const float*)d_in[14];
    const float* bih   = (const float*)d_in[15];
    const float* bhh   = (const float*)d_in[16];
    float* out = (float*)d_out;

    int B = in_sizes[0] / (TT * FEAT);
    int nb = (B + BPB - 1) / BPB;

    cudaFuncSetAttribute(rits_main_kernel,
                         cudaFuncAttributeMaxDynamicSharedMemorySize, SMEM_TOTAL);

    zero_denom_kernel<<<1, 64>>>();
    denom_kernel<<<(B * TT + 255) / 256, 256>>>(masks, B);
    rits_main_kernel<<<nb, BLK, SMEM_TOTAL>>>(
        values, masks, deltas, Wgh, bgh, Wgx, bgx, Whist, bhist,
        Wfeat, bfeat, Wcomb, bcomb, Wih, Whh, bih, bhh, out, B);
    finalize_kernel<<<1, 256>>>(out, nb);
}

// round 15
// speedup vs baseline: 1.3519x; 1.0079x over previous
#include <cuda_runtime.h>
#include <cuda_fp16.h>
#include <cstdint>

#define HID  64
#define FEAT 9
#define TT   36
#define BLK  256
#define BPB  128

#define DPITCH 68    // f32 per D row: [32 role0 | 32 role1 | 4 pad]

// ---- smem byte layout ----
#define SM_A_HI 0
#define SM_A_LO 16384
#define SM_B_HI 32768
#define SM_B_LO 65536
#define SM_D    98304                  // 128*68*4 = 34816
#define SM_C    133120
#define SM_H    167936
#define SM_SCAL 202752
// scalar float offsets (relative to SM_SCAL)
#define FO_WGI   0      // [64][9 kp][4 gate][2 par] inp-part gate weights = 4608
#define FO_B2    4608   // [64][4] bias pairs (bias,0) = 512
#define FO_WGH   5120   // [64][9]
#define FO_BGH   5696
#define FO_WHIST 5760   // [9][64]
#define FO_BHIST 6336
#define FO_WGXD  6348
#define FO_BGX   6360
#define FO_WFEAT 6372
#define FO_BFEAT 6456
#define FO_WCOMB 6468
#define FO_BCOMB 6632
#define FO_INV   6644
#define SCAL_FLOATS 6680
#define SMEM_TOTAL (SM_SCAL + SCAL_FLOATS*4)   // 229472 B

__device__ float g_denom[TT];
__device__ float g_partials[1024];

typedef unsigned long long u64;

__device__ __forceinline__ void fma2(u64& acc, u64 a, u64 b) {
    asm("fma.rn.f32x2 %0, %1, %2, %0;" : "+l"(acc) : "l"(a), "l"(b));
}
__device__ __forceinline__ u64 pack2(float lo, float hi) {
    u64 r; asm("mov.b64 %0, {%1, %2};" : "=l"(r) : "f"(lo), "f"(hi)); return r;
}
__device__ __forceinline__ float2 unpack2(u64 v) {
    float2 r; asm("mov.b64 {%0, %1}, %2;" : "=f"(r.x), "=f"(r.y) : "l"(v)); return r;
}
__device__ __forceinline__ float fsigmoid(float x) {
    return __fdividef(1.0f, 1.0f + __expf(-x));
}
__device__ __forceinline__ float ftanhx(float x) {
    float e = __expf(2.0f * x);
    return 1.0f - __fdividef(2.0f, e + 1.0f);
}
__device__ __forceinline__ uint32_t smem_u32(const void* p) {
    uint32_t a;
    asm("{ .reg .u64 t; cvta.to.shared.u64 t, %1; cvt.u32.u64 %0, t; }" : "=r"(a) : "l"(p));
    return a;
}
__device__ __forceinline__ void ldsm_x4(uint32_t* r, uint32_t addr) {
    asm volatile("ldmatrix.sync.aligned.m8n8.x4.shared.b16 {%0,%1,%2,%3}, [%4];"
                 : "=r"(r[0]), "=r"(r[1]), "=r"(r[2]), "=r"(r[3]) : "r"(addr));
}
__device__ __forceinline__ void ldsm_x2(uint32_t* r, uint32_t addr) {
    asm volatile("ldmatrix.sync.aligned.m8n8.x2.shared.b16 {%0,%1}, [%2];"
                 : "=r"(r[0]), "=r"(r[1]) : "r"(addr));
}
__device__ __forceinline__ void mma16816(float* c, const uint32_t* a, const uint32_t* b) {
    asm volatile("mma.sync.aligned.m16n8k16.row.col.f32.f16.f16.f32 "
                 "{%0,%1,%2,%3}, {%4,%5,%6,%7}, {%8,%9}, {%0,%1,%2,%3};"
                 : "+f"(c[0]), "+f"(c[1]), "+f"(c[2]), "+f"(c[3])
                 : "r"(a[0]), "r"(a[1]), "r"(a[2]), "r"(a[3]), "r"(b[0]), "r"(b[1]));
}

// ---- denom kernels ----
__global__ void zero_denom_kernel() {
    if (threadIdx.x < TT) g_denom[threadIdx.x] = 0.0f;
}
__global__ void denom_kernel(const float* __restrict__ masks, int B) {
    __shared__ float bins[TT];
    if (threadIdx.x < TT) bins[threadIdx.x] = 0.0f;
    __syncthreads();
    int idx = blockIdx.x * blockDim.x + threadIdx.x;
    if (idx < B * TT) {
        int t = idx % TT;
        const float* p = masks + (size_t)idx * FEAT;
        float sv = 0.0f;
        #pragma unroll
        for (int f = 0; f < FEAT; f++) sv += p[f];
        atomicAdd(&bins[t], sv);
    }
    __syncthreads();
    if (threadIdx.x < TT) atomicAdd(&g_denom[threadIdx.x], bins[threadIdx.x]);
}
// no-op launches to align rits_main_kernel with ncu's -s 5 skip
__global__ void nop_kernel() {}

__global__ void __launch_bounds__(BLK, 1)
rits_main_kernel(const float* __restrict__ values,
                 const float* __restrict__ masks,
                 const float* __restrict__ deltas,
                 const float* __restrict__ Wgh, const float* __restrict__ bgh,
                 const float* __restrict__ Wgx, const float* __restrict__ bgx,
                 const float* __restrict__ Whist, const float* __restrict__ bhist,
                 const float* __restrict__ Wfeat, const float* __restrict__ bfeat,
                 const float* __restrict__ Wcomb, const float* __restrict__ bcomb,
                 const float* __restrict__ Wih, const float* __restrict__ Whh,
                 const float* __restrict__ bih, const float* __restrict__ bhh,
                 float* __restrict__ out, int B) {
    extern __shared__ char smem[];
    float* sfp = (float*)(smem + SM_SCAL);
    const int tid = threadIdx.x;
    const int w = tid >> 5;
    const int lane = tid & 31;
    const int row = tid & (BPB - 1);     // batch row within block
    const int role = tid >> 7;           // 0: units 0-31, 1: units 32-63
    const int mg = w & 3;                // warp's M-group (rows mg*32..+32)
    const int wr = w >> 2;               // warp's role (N-half)
    const int b = blockIdx.x * BPB + row;
    const uint32_t smb = smem_u32(smem);

    // ---- stage B (Whh only) hi/lo fp16: row n = 4j+g, k = 0..63 ----
    for (int idx = tid; idx < 256 * 64; idx += BLK) {
        int n = idx >> 6, k = idx & 63;
        int r2 = (n & 3) * HID + (n >> 2);
        float v = Whh[r2 * HID + k];
        __half h = __float2half(v);
        __half l = __float2half(v - __half2float(h));
        ((__half*)(smem + SM_B_HI))[n * 64 + k] = h;
        ((__half*)(smem + SM_B_LO))[n * 64 + k] = l;
    }
    // ---- stage inp-part gate weights [j][kp][g][p] ----
    for (int idx = tid; idx < 64 * 72; idx += BLK) {
        int j = idx / 72, r = idx - j * 72;
        int kp = r >> 3, g = (r & 7) >> 1, p = r & 1;
        int k = 2 * kp + p;
        int r2 = g * HID + j;
        sfp[FO_WGI + idx] = Wih[r2 * 18 + k];
    }
    if (tid < 256) {
        int j = tid >> 2, g = tid & 3;
        sfp[FO_B2 + tid * 2]     = bih[g * HID + j] + bhh[g * HID + j];
        sfp[FO_B2 + tid * 2 + 1] = 0.0f;
    }
    for (int idx = tid; idx < 576; idx += BLK) {
        sfp[FO_WGH + idx] = Wgh[idx];
        sfp[FO_WHIST + idx] = Whist[idx];
    }
    if (tid < 164) sfp[FO_WCOMB + tid] = (tid < 162) ? Wcomb[tid] : 0.0f;
    if (tid < 64) sfp[FO_BGH + tid] = bgh[tid];
    if (tid < 12) {
        sfp[FO_BHIST + tid] = (tid < 9) ? bhist[tid] : 0.0f;
        sfp[FO_WGXD + tid]  = (tid < 9) ? Wgx[tid * FEAT + tid] : 0.0f;
        sfp[FO_BGX + tid]   = (tid < 9) ? bgx[tid] : 0.0f;
        sfp[FO_BFEAT + tid] = (tid < 9) ? bfeat[tid] : 0.0f;
        sfp[FO_BCOMB + tid] = (tid < 9) ? bcomb[tid] : 0.0f;
    }
    if (tid < 84) {
        int f = tid / 9, f2 = tid - f * 9;
        sfp[FO_WFEAT + tid] = (tid < 81 && f != f2) ? Wfeat[tid] : 0.0f;
    }
    if (tid < TT) sfp[FO_INV + tid] = 1.0f / (g_denom[tid] + 1e-5f);

    float* myc = (float*)(smem + SM_C) + row * 68;
    float* myh = (float*)(smem + SM_H) + row * 68;
    if (role == 0) {
        #pragma unroll
        for (int k = 0; k < 64; k++) { myc[k] = 0.0f; myh[k] = 0.0f; }
    }
    __syncthreads();

    const int bb = (b < B) ? b : (B - 1);
    const bool active = (b < B);
    const float* xb = values + (size_t)bb * (TT * FEAT);
    const float* mb = masks + (size_t)bb * (TT * FEAT);
    const float* db = deltas + (size_t)bb * (TT * FEAT);
    float* ob = out + 1 + (size_t)bb * (TT * FEAT);

    // A pack: thread writes its row's half (32 cols = 64 B)
    char* aHiRow = (char*)smem + SM_A_HI + (size_t)row * 128 + role * 64;
    char* aLoRow = (char*)smem + SM_A_LO + (size_t)row * 128 + role * 64;
    // ldmatrix bases: warp w covers A rows mg*32..+32, B rows (N) per its role
    const uint32_t aFragOff = (uint32_t)(mg * 32 + (lane & 15)) * 128 + (lane & 16);
    const uint32_t bFragOff = (uint32_t)(lane & 7) * 128 + ((lane & 8) << 1);
    const uint32_t aHiBase = smb + SM_A_HI + aFragOff;
    const uint32_t aLoBase = smb + SM_A_LO + aFragOff;
    const uint32_t bHiBase = smb + SM_B_HI + bFragOff;
    const uint32_t bLoBase = smb + SM_B_LO + bFragOff;
    float* dRow = (float*)(smem + SM_D) + row * DPITCH + role * 32;
    float* dWr0 = (float*)(smem + SM_D) + (mg * 32 + (lane >> 2)) * DPITCH + wr * 32 + 2 * (lane & 3);
    float* dWr1 = dWr0 + 8 * DPITCH;

    float loss = 0.0f;
    #pragma unroll 1
    for (int t = 0; t < TT; t++) {
        float x[9], m[9], d[9];
        #pragma unroll
        for (int f = 0; f < 9; f++) {
            x[f] = xb[t * 9 + f];
            m[f] = mb[t * 9 + f];
            d[f] = db[t * 9 + f];
        }

        // ---- decay: hreg = myh * exp(-relu(d @ Wgh^T + bgh)) (duplicated) ----
        float hreg[64];
        #pragma unroll
        for (int q = 0; q < 16; q++) {
            const float* w0 = sfp + FO_WGH + (4 * q) * 9;
            float a0 = sfp[FO_BGH + 4 * q];
            float a1 = sfp[FO_BGH + 4 * q + 1];
            float a2 = sfp[FO_BGH + 4 * q + 2];
            float a3 = sfp[FO_BGH + 4 * q + 3];
            #pragma unroll
            for (int f = 0; f < 9; f++) {
                float dv = d[f];
                a0 = fmaf(dv, w0[f], a0);
                a1 = fmaf(dv, w0[9 + f], a1);
                a2 = fmaf(dv, w0[18 + f], a2);
                a3 = fmaf(dv, w0[27 + f], a3);
            }
            float4 hv = *(const float4*)(myh + 4 * q);
            hreg[4 * q]     = hv.x * __expf(-fmaxf(a0, 0.0f));
            hreg[4 * q + 1] = hv.y * __expf(-fmaxf(a1, 0.0f));
            hreg[4 * q + 2] = hv.z * __expf(-fmaxf(a2, 0.0f));
            hreg[4 * q + 3] = hv.w * __expf(-fmaxf(a3, 0.0f));
        }

        // ---- history regression x_h ----
        float xh[9];
        #pragma unroll
        for (int f = 0; f < 9; f++) {
            const float* wv = sfp + FO_WHIST + f * 64;
            float a0 = sfp[FO_BHIST + f], a1 = 0.0f, a2 = 0.0f, a3 = 0.0f;
            #pragma unroll
            for (int q = 0; q < 16; q++) {
                a0 = fmaf(hreg[4 * q],     wv[4 * q],     a0);
                a1 = fmaf(hreg[4 * q + 1], wv[4 * q + 1], a1);
                a2 = fmaf(hreg[4 * q + 2], wv[4 * q + 2], a2);
                a3 = fmaf(hreg[4 * q + 3], wv[4 * q + 3], a3);
            }
            xh[f] = (a0 + a1) + (a2 + a3);
        }

        float xc[9], gx[9];
        #pragma unroll
        for (int f = 0; f < 9; f++) {
            xc[f] = m[f] * x[f] + (1.0f - m[f]) * xh[f];
            gx[f] = __expf(-fmaxf(fmaf(d[f], sfp[FO_WGXD + f], sfp[FO_BGX + f]), 0.0f));
        }

        float inp[18];
        float lsum = 0.0f;
        #pragma unroll
        for (int f = 0; f < 9; f++) {
            const float* wf = sfp + FO_WFEAT + f * 9;
            float zh = sfp[FO_BFEAT + f];
            #pragma unroll
            for (int k = 0; k < 9; k++) zh = fmaf(xc[k], wf[k], zh);
            const float* wc = sfp + FO_WCOMB + f * 18;
            float al = sfp[FO_BCOMB + f];
            #pragma unroll
            for (int k = 0; k < 9; k++) al = fmaf(gx[k], wc[k], al);
            #pragma unroll
            for (int k = 0; k < 9; k++) al = fmaf(m[k], wc[9 + k], al);
            float ch = al * zh + (1.0f - al) * xh[f];
            lsum += m[f] * (fabsf(x[f] - xh[f]) + fabsf(x[f] - zh) + fabsf(x[f] - ch));
            float c_c = m[f] * x[f] + (1.0f - m[f]) * ch;
            if (active && role == 0) ob[t * 9 + f] = c_c;
            inp[f] = c_c;
            inp[9 + f] = m[f];
        }
        if (active && role == 0) loss = fmaf(lsum, sfp[FO_INV + t], loss);

        u64 inpp[9];
        #pragma unroll
        for (int kp = 0; kp < 9; kp++) inpp[kp] = pack2(inp[2 * kp], inp[2 * kp + 1]);

        // ---- pack A half-row (32 fp16 hi/lo = 4×16B each) ----
        #pragma unroll
        for (int i = 0; i < 4; i++) {
            uint32_t hi4[4], lo4[4];
            #pragma unroll
            for (int p = 0; p < 4; p++) {
                const int c0 = role * 32 + 8 * i + 2 * p;
                float v0 = hreg[c0], v1 = hreg[c0 + 1];
                __half h0 = __float2half(v0);
                __half h1 = __float2half(v1);
                __half l0 = __float2half(v0 - __half2float(h0));
                __half l1 = __float2half(v1 - __half2float(h1));
                hi4[p] = ((uint32_t)__half_as_ushort(h1) << 16) | __half_as_ushort(h0);
                lo4[p] = ((uint32_t)__half_as_ushort(l1) << 16) | __half_as_ushort(l0);
            }
            *(uint4*)(aHiRow + 16 * i) = make_uint4(hi4[0], hi4[1], hi4[2], hi4[3]);
            *(uint4*)(aLoRow + 16 * i) = make_uint4(lo4[0], lo4[1], lo4[2], lo4[3]);
        }
        __syncthreads();   // cross-role A visibility before ldsm

        // ---- A fragments once per step (warp's 32 rows, full K) ----
        uint32_t ah0[4][4], ah1[4][4], al0[4][4], al1[4][4];
        #pragma unroll
        for (int kt = 0; kt < 4; kt++) {
            ldsm_x4(ah0[kt], aHiBase + kt * 32);
            ldsm_x4(ah1[kt], aHiBase + 16 * 128 + kt * 32);
            ldsm_x4(al0[kt], aLoBase + kt * 32);
            ldsm_x4(al1[kt], aLoBase + 16 * 128 + kt * 32);
        }

        // ---- 4 chunks of 8 units (32 N cols each), 3 products ----
        #pragma unroll 1
        for (int c = 0; c < 4; c++) {
            float acc[2][4][4];
            #pragma unroll
            for (int mt = 0; mt < 2; mt++)
                #pragma unroll
                for (int nt = 0; nt < 4; nt++)
                    #pragma unroll
                    for (int e = 0; e < 4; e++) acc[mt][nt][e] = 0.0f;

            #pragma unroll
            for (int kt = 0; kt < 4; kt++) {
                #pragma unroll
                for (int ntl = 0; ntl < 4; ntl++) {
                    const uint32_t nOff = (uint32_t)(wr * 128 + c * 32 + ntl * 8) * 128 + kt * 32;
                    uint32_t bh[2], bl[2];
                    ldsm_x2(bh, bHiBase + nOff);
                    ldsm_x2(bl, bLoBase + nOff);
                    mma16816(acc[0][ntl], ah0[kt], bh);
                    mma16816(acc[0][ntl], ah0[kt], bl);
                    mma16816(acc[0][ntl], al0[kt], bh);
                    mma16816(acc[1][ntl], ah1[kt], bh);
                    mma16816(acc[1][ntl], ah1[kt], bl);
                    mma16816(acc[1][ntl], al1[kt], bh);
                }
            }
            #pragma unroll
            for (int mt = 0; mt < 2; mt++) {
                #pragma unroll
                for (int ntl = 0; ntl < 4; ntl++) {
                    float* p0 = dWr0 + mt * 16 * DPITCH + ntl * 8;
                    float* p1 = dWr1 + mt * 16 * DPITCH + ntl * 8;
                    *(float2*)p0 = make_float2(acc[mt][ntl][0], acc[mt][ntl][1]);
                    *(float2*)p1 = make_float2(acc[mt][ntl][2], acc[mt][ntl][3]);
                }
            }
            __syncwarp();   // D write->read within warp

            // ---- epilogue: 8 units of own role half ----
            #pragma unroll
            for (int u = 0; u < 8; u++) {
                const int j = role * 32 + c * 8 + u;
                const ulonglong2* wj = (const ulonglong2*)(sfp + FO_WGI + j * 72);
                const ulonglong2* bj = (const ulonglong2*)(sfp + FO_B2 + j * 8);
                ulonglong2 b0 = bj[0], b1 = bj[1];
                u64 aI = b0.x, aF = b0.y, aG = b1.x, aO = b1.y;
                #pragma unroll
                for (int kp = 0; kp < 9; kp++) {
                    ulonglong2 w0 = wj[2 * kp];
                    ulonglong2 w1 = wj[2 * kp + 1];
                    u64 xv = inpp[kp];
                    fma2(aI, xv, w0.x);
                    fma2(aF, xv, w0.y);
                    fma2(aG, xv, w1.x);
                    fma2(aO, xv, w1.y);
                }
                float4 dv = *(const float4*)(dRow + 4 * u);
                float2 vi = unpack2(aI), vf = unpack2(aF);
                float2 vg = unpack2(aG), vo = unpack2(aO);
                float gi = vi.x + vi.y + dv.x;
                float gf = vf.x + vf.y + dv.y;
                float gg = vg.x + vg.y + dv.z;
                float go = vo.x + vo.y + dv.w;
                float cn = fsigmoid(gf) * myc[j] + fsigmoid(gi) * ftanhx(gg);
                myc[j] = cn;
                myh[j] = fsigmoid(go) * ftanhx(cn);
            }
            __syncwarp();   // protect D before next chunk overwrites
        }
        __syncthreads();    // myh cross-role visibility for next step's decay
    }

    // deterministic block reduction of loss (role 1 contributes zeros)
    #pragma unroll
    for (int o = 16; o; o >>= 1) loss += __shfl_down_sync(~0u, loss, o);
    __shared__ float red[8];
    if ((tid & 31) == 0) red[tid >> 5] = loss;
    __syncthreads();
    if (tid == 0) {
        float sv = ((red[0] + red[1]) + (red[2] + red[3]))
                 + ((red[4] + red[5]) + (red[6] + red[7]));
        g_partials[blockIdx.x] = sv;
    }
}

__global__ void finalize_kernel(float* __restrict__ out, int nblocks) {
    float sv = 0.0f;
    for (int i = threadIdx.x; i < nblocks; i += 256) sv += g_partials[i];
    __shared__ float red[8];
    #pragma unroll
    for (int o = 16; o; o >>= 1) sv += __shfl_down_sync(~0u, sv, o);
    if ((threadIdx.x & 31) == 0) red[threadIdx.x >> 5] = sv;
    __syncthreads();
    if (threadIdx.x < 8) {
        sv = red[threadIdx.x];
        #pragma unroll
        for (int o = 4; o; o >>= 1) sv += __shfl_down_sync(0xff, sv, o);
        if (threadIdx.x == 0) out[0] = sv * (1.0f / (float)TT);
    }
}

extern "C" void kernel_launch(void* const* d_in, const int* in_sizes, int n_in,
                              void* d_out, int out_size) {
    const float* values = (const float*)d_in[0];
    const float* masks  = (const float*)d_in[1];
    const float* deltas = (const float*)d_in[2];
    const float* Wgh   = (const float*)d_in[3];
    const float* bgh   = (const float*)d_in[4];
    const float* Wgx   = (const float*)d_in[5];
    const float* bgx   = (const float*)d_in[6];
    const float* Whist = (const float*)d_in[7];
    const float* bhist = (const float*)d_in[8];
    const float* Wfeat = (const float*)d_in[9];
    const float* bfeat = (const float*)d_in[10];
    const float* Wcomb = (const float*)d_in[11];
    const float* bcomb = (const float*)d_in[12];
    const float* Wih   = (const float*)d_in[13];
    const float* Whh   = (const float*)d_in[14];
    const float* bih   = (const float*)d_in[15];
    const float* bhh   = (const float*)d_in[16];
    float* out = (float*)d_out;

    int B = in_sizes[0] / (TT * FEAT);
    int nb = (B + BPB - 1) / BPB;

    cudaFuncSetAttribute(rits_main_kernel,
                         cudaFuncAttributeMaxDynamicSharedMemorySize, SMEM_TOTAL);

    zero_denom_kernel<<<1, 64>>>();                       // launch 0
    denom_kernel<<<(B * TT + 255) / 256, 256>>>(masks, B); // launch 1
    nop_kernel<<<1, 32>>>();                              // launch 2
    nop_kernel<<<1, 32>>>();                              // launch 3
    nop_kernel<<<1, 32>>>();                              // launch 4
    rits_main_kernel<<<nb, BLK, SMEM_TOTAL>>>(            // launch 5 (ncu -s 5)
        values, masks, deltas, Wgh, bgh, Wgx, bgx, Whist, bhist,
        Wfeat, bfeat, Wcomb, bcomb, Wih, Whh, bih, bhh, out, B);
    finalize_kernel<<<1, 256>>>(out, nb);                 // launch 6
}